// round 11
// baseline (speedup 1.0000x reference)
#include <cuda_runtime.h>
#include <math.h>
#include <stdint.h>

#define BB      8
#define NHEADS  8
#define HD      32
#define NN      1024
#define CDIM    256
#define TABLE_SZ 3969
#define CPBH    512
#define LOG2E   1.4426950408889634f

// ---------------- scratch (bf16 hi/lo word layouts) -------------------------
__device__ __align__(16) uint32_t g_q2h[BB * NHEADS * NN * 16];
__device__ __align__(16) uint32_t g_q2l[BB * NHEADS * NN * 16];
__device__ __align__(16) uint32_t g_kh [BB * NHEADS * NN * 16];
__device__ __align__(16) uint32_t g_kl [BB * NHEADS * NN * 16];
__device__ __align__(16) uint32_t g_vth[BB * NHEADS * HD * (NN / 2)];
__device__ __align__(16) uint32_t g_vtl[BB * NHEADS * HD * (NN / 2)];
__device__ __align__(16) uint32_t g_bias[NHEADS * NN * (NN / 2)];    // bf16x2 (base-2 units)
__device__ float g_tab[NHEADS * TABLE_SZ];     // scaled by log2e
__device__ float g_tabmax[NHEADS];
__device__ float g_smax[BB * NHEADS * NN];     // ||qs_n|| (base-2 units)
// pre-split planes: [row][K/2] word layout
__device__ __align__(16) uint32_t g_xh [BB * NN * (CDIM / 2)];
__device__ __align__(16) uint32_t g_xl [BB * NN * (CDIM / 2)];
__device__ __align__(16) uint32_t g_aoh[BB * NN * (CDIM / 2)];
__device__ __align__(16) uint32_t g_aol[BB * NN * (CDIM / 2)];

// ---------------- helpers -----------------------------------------------------
__device__ __forceinline__ uint32_t bf16x2(float lo, float hi) {
    uint32_t d;
    asm("cvt.rn.bf16x2.f32 %0, %1, %2;" : "=r"(d) : "f"(hi), "f"(lo));
    return d;
}
__device__ __forceinline__ void bfsplit2(float x0, float x1, uint32_t &hi, uint32_t &lo) {
    uint32_t h = bf16x2(x0, x1);
    float r0 = x0 - __uint_as_float(h << 16);
    float r1 = x1 - __uint_as_float(h & 0xffff0000u);
    hi = h;
    lo = bf16x2(r0, r1);
}
__device__ __forceinline__ float ex2f(float x) {
    float y;
    asm("ex2.approx.f32 %0, %1;" : "=f"(y) : "f"(x));
    return y;
}
__device__ __forceinline__ void mma_bf16(float c[4],
                                         uint32_t a0, uint32_t a1, uint32_t a2, uint32_t a3,
                                         uint32_t b0, uint32_t b1) {
    asm volatile(
        "mma.sync.aligned.m16n8k16.row.col.f32.bf16.bf16.f32 "
        "{%0,%1,%2,%3}, {%4,%5,%6,%7}, {%8,%9}, {%0,%1,%2,%3};"
        : "+f"(c[0]), "+f"(c[1]), "+f"(c[2]), "+f"(c[3])
        : "r"(a0), "r"(a1), "r"(a2), "r"(a3), "r"(b0), "r"(b1));
}
__device__ __forceinline__ void cp16(uint32_t dst, const void* src) {
    asm volatile("cp.async.cg.shared.global [%0], [%1], 16;" :: "r"(dst), "l"(src));
}

// ---------------- f32 -> hi/lo plane converter --------------------------------
__global__ __launch_bounds__(256) void conv_split(const float* __restrict__ src,
                                                  uint32_t* __restrict__ dh,
                                                  uint32_t* __restrict__ dl,
                                                  int npairs) {
    int i = blockIdx.x * blockDim.x + threadIdx.x;     // handles pairs 2i, 2i+1
    if (2 * i + 1 < npairs) {
        float4 v = *(const float4*)&src[4 * i];
        uint32_t h0, l0, h1, l1;
        bfsplit2(v.x, v.y, h0, l0);
        bfsplit2(v.z, v.w, h1, l1);
        *(uint2*)&dh[2 * i] = make_uint2(h0, h1);
        *(uint2*)&dl[2 * i] = make_uint2(l0, l1);
    }
}

// ---------------- CPB MLP (SMEM-staged weights, warp-per-entry) --------------
__global__ __launch_bounds__(256) void cpb_kernel(const float* __restrict__ coords,
                                                  const float* __restrict__ fc1w,
                                                  const float* __restrict__ fc1b,
                                                  const float* __restrict__ fc2w,
                                                  const float* __restrict__ fc2b) {
    __shared__ float s_w1[CPBH * 2];
    __shared__ float s_b1[CPBH];
    __shared__ float s_w2[NHEADS * CPBH];
    const int tid = threadIdx.x;
    for (int i = tid; i < CPBH * 2; i += 256) s_w1[i] = fc1w[i];
    for (int i = tid; i < CPBH; i += 256) s_b1[i] = fc1b[i];
    for (int i = tid; i < NHEADS * CPBH; i += 256) s_w2[i] = fc2w[i];
    __syncthreads();
    const int warp = tid >> 5, lane = tid & 31;
#pragma unroll
    for (int e = 0; e < 4; e++) {
        int t = blockIdx.x * 32 + warp * 4 + e;
        if (t >= TABLE_SZ) continue;
        float c0 = coords[2 * t], c1 = coords[2 * t + 1];
        float acc[NHEADS];
#pragma unroll
        for (int h = 0; h < NHEADS; h++) acc[h] = 0.f;
#pragma unroll 4
        for (int j = lane; j < CPBH; j += 32) {
            float hv = fmaxf(c0 * s_w1[2 * j] + c1 * s_w1[2 * j + 1] + s_b1[j], 0.f);
#pragma unroll
            for (int h = 0; h < NHEADS; h++) acc[h] += hv * s_w2[h * CPBH + j];
        }
#pragma unroll
        for (int h = 0; h < NHEADS; h++) {
#pragma unroll
            for (int o = 16; o; o >>= 1) acc[h] += __shfl_xor_sync(0xffffffffu, acc[h], o);
            if (lane == 0) g_tab[h * TABLE_SZ + t] = (acc[h] + fc2b[h]) * LOG2E;
        }
    }
}

// ---------------- bias expand + per-head max ----------------------------------
__global__ __launch_bounds__(256) void bias_expand(const int* __restrict__ rpi) {
    __shared__ float tab_s[TABLE_SZ];
    __shared__ float redm[8];
    int h = blockIdx.x >> 6;
    int chunk = blockIdx.x & 63;
    for (int i = threadIdx.x; i < TABLE_SZ; i += 256) tab_s[i] = g_tab[h * TABLE_SZ + i];
    __syncthreads();
    if (chunk == 0) {
        float m = -1e30f;
        for (int i = threadIdx.x; i < TABLE_SZ; i += 256) m = fmaxf(m, tab_s[i]);
#pragma unroll
        for (int o = 16; o; o >>= 1) m = fmaxf(m, __shfl_xor_sync(0xffffffffu, m, o));
        if ((threadIdx.x & 31) == 0) redm[threadIdx.x >> 5] = m;
        __syncthreads();
        if (threadIdx.x == 0) {
            float mm = redm[0];
            for (int w = 1; w < 8; w++) mm = fmaxf(mm, redm[w]);
            g_tabmax[h] = mm;
        }
    }
    for (int i = threadIdx.x; i < 16 * 512; i += 256) {
        int nl = i >> 9, mw = i & 511;
        int n = chunk * 16 + nl;
        int2 id = *(const int2*)&rpi[(size_t)n * NN + 2 * mw];
        g_bias[((size_t)h * NN + n) * 512 + mw] = bf16x2(tab_s[id.x], tab_s[id.y]);
    }
}

// ---------------- fused qkv GEMM (A from planes) + l2norm + split ------------
__global__ __launch_bounds__(256) void gemm_qkv_fused(
        const float* __restrict__ W,
        const float* __restrict__ bias,
        const float* __restrict__ qe, const float* __restrict__ temp) {
    extern __shared__ uint32_t smg[];
    uint32_t* Ah = smg;               // [128][20]
    uint32_t* Al = Ah + 128 * 20;
    uint32_t* Wh = Al + 128 * 20;     // [64][20]
    uint32_t* Wl = Wh + 64 * 20;
    const int bm = blockIdx.y * 128, bn = blockIdx.x * 64;
    const int tid = threadIdx.x, lane = tid & 31, warp = tid >> 5;
    const int wm = (warp >> 1) * 32, wn = (warp & 1) * 32;
    const int r = lane >> 2, c = lane & 3;
    const int K = CDIM;

    float acc[2][4][4];
#pragma unroll
    for (int mt = 0; mt < 2; mt++)
#pragma unroll
        for (int nt = 0; nt < 4; nt++)
#pragma unroll
            for (int q = 0; q < 4; q++) acc[mt][nt][q] = 0.f;

    uint2 pah[4], pal[4];
    float4 pw[2];
#pragma unroll
    for (int i = 0; i < 4; i++) {
        int v = tid + i * 256; int row = v >> 3, wq = (v & 7) * 2;
        pah[i] = *(const uint2*)&g_xh[(size_t)(bm + row) * 128 + wq];
        pal[i] = *(const uint2*)&g_xl[(size_t)(bm + row) * 128 + wq];
    }
#pragma unroll
    for (int i = 0; i < 2; i++) {
        int v = tid + i * 256; int row = v >> 3, kq = (v & 7) * 4;
        pw[i] = *(const float4*)&W[(size_t)(bn + row) * K + kq];
    }

    for (int k0 = 0; k0 < K; k0 += 32) {
#pragma unroll
        for (int i = 0; i < 4; i++) {
            int v = tid + i * 256; int row = v >> 3, wq = (v & 7) * 2;
            *(uint2*)&Ah[row * 20 + wq] = pah[i];
            *(uint2*)&Al[row * 20 + wq] = pal[i];
        }
#pragma unroll
        for (int i = 0; i < 2; i++) {
            int v = tid + i * 256; int row = v >> 3, kq = (v & 7) * 4;
            uint32_t h, l;
            bfsplit2(pw[i].x, pw[i].y, h, l);
            Wh[row * 20 + (kq >> 1)] = h;  Wl[row * 20 + (kq >> 1)] = l;
            bfsplit2(pw[i].z, pw[i].w, h, l);
            Wh[row * 20 + (kq >> 1) + 1] = h;  Wl[row * 20 + (kq >> 1) + 1] = l;
        }
        __syncthreads();
        if (k0 + 32 < K) {
#pragma unroll
            for (int i = 0; i < 4; i++) {
                int v = tid + i * 256; int row = v >> 3, wq = (v & 7) * 2;
                pah[i] = *(const uint2*)&g_xh[(size_t)(bm + row) * 128 + (k0 + 32) / 2 + wq];
                pal[i] = *(const uint2*)&g_xl[(size_t)(bm + row) * 128 + (k0 + 32) / 2 + wq];
            }
#pragma unroll
            for (int i = 0; i < 2; i++) {
                int v = tid + i * 256; int row = v >> 3, kq = (v & 7) * 4;
                pw[i] = *(const float4*)&W[(size_t)(bn + row) * K + k0 + 32 + kq];
            }
        }
#pragma unroll
        for (int kt = 0; kt < 2; kt++) {
            uint32_t ah[2][4], al[2][4];
#pragma unroll
            for (int mt = 0; mt < 2; mt++) {
                int r0 = (wm + mt * 16 + r) * 20 + kt * 8 + c;
                int r1 = r0 + 8 * 20;
                ah[mt][0] = Ah[r0];     al[mt][0] = Al[r0];
                ah[mt][1] = Ah[r1];     al[mt][1] = Al[r1];
                ah[mt][2] = Ah[r0 + 4]; al[mt][2] = Al[r0 + 4];
                ah[mt][3] = Ah[r1 + 4]; al[mt][3] = Al[r1 + 4];
            }
#pragma unroll
            for (int nt = 0; nt < 4; nt++) {
                int w0 = (wn + nt * 8 + r) * 20 + kt * 8 + c;
                uint32_t bh0 = Wh[w0], bh1 = Wh[w0 + 4];
                uint32_t bl0 = Wl[w0], bl1 = Wl[w0 + 4];
#pragma unroll
                for (int mt = 0; mt < 2; mt++) {
                    mma_bf16(acc[mt][nt], ah[mt][0], ah[mt][1], ah[mt][2], ah[mt][3], bh0, bh1);
                    mma_bf16(acc[mt][nt], al[mt][0], al[mt][1], al[mt][2], al[mt][3], bh0, bh1);
                    mma_bf16(acc[mt][nt], ah[mt][0], ah[mt][1], ah[mt][2], ah[mt][3], bl0, bl1);
                }
            }
        }
        __syncthreads();
    }

    // ---- fused epilogue ----
    const int col_base = bn + wn;
    const int region = col_base >> 8;             // 0=q, 1=k, 2=v
    const int head = (col_base >> 5) & 7;
    float scale_h = 0.f, qe0[4], qe1[4];
    if (region == 0) {
        scale_h = log1pf(expf(temp[head])) * logf(1024.0f) * LOG2E;
#pragma unroll
        for (int nt = 0; nt < 4; nt++) {
            qe0[nt] = qe[head * HD + nt * 8 + 2 * c];
            qe1[nt] = qe[head * HD + nt * 8 + 2 * c + 1];
        }
    }
#pragma unroll
    for (int mt = 0; mt < 2; mt++) {
#pragma unroll
        for (int half = 0; half < 2; half++) {
            int row = bm + wm + mt * 16 + r + half * 8;
            int bq = row >> 10, n = row & 1023;
            float v0[4], v1[4];
#pragma unroll
            for (int nt = 0; nt < 4; nt++) {
                int cg = col_base + nt * 8 + 2 * c;
                v0[nt] = acc[mt][nt][half * 2]     + bias[cg];
                v1[nt] = acc[mt][nt][half * 2 + 1] + bias[cg + 1];
            }
            if (region < 2) {
                float ss = 0.f;
#pragma unroll
                for (int nt = 0; nt < 4; nt++) ss += v0[nt] * v0[nt] + v1[nt] * v1[nt];
                ss += __shfl_xor_sync(0xffffffffu, ss, 1);
                ss += __shfl_xor_sync(0xffffffffu, ss, 2);
                float inv = 1.f / fmaxf(sqrtf(ss), 1e-12f);
                size_t base = ((size_t)(bq * 8 + head) * NN + n) * 16;
                float ss2 = 0.f;
#pragma unroll
                for (int nt = 0; nt < 4; nt++) {
                    float a = v0[nt] * inv, bv = v1[nt] * inv;
                    if (region == 0) {
                        a  = (a  + qe0[nt]) * scale_h;
                        bv = (bv + qe1[nt]) * scale_h;
                        ss2 += a * a + bv * bv;
                    }
                    uint32_t hh, ll;
                    bfsplit2(a, bv, hh, ll);
                    size_t w = base + nt * 4 + c;
                    if (region == 0) { g_q2h[w] = hh; g_q2l[w] = ll; }
                    else             { g_kh[w]  = hh; g_kl[w]  = ll; }
                }
                if (region == 0) {
                    ss2 += __shfl_xor_sync(0xffffffffu, ss2, 1);
                    ss2 += __shfl_xor_sync(0xffffffffu, ss2, 2);
                    if (c == 0)
                        g_smax[(size_t)(bq * 8 + head) * NN + n] = sqrtf(ss2);
                }
            } else {
                size_t bh = (size_t)(bq * 8 + head);
                int np = n >> 1;
                bool evenr = ((r & 1) == 0);
#pragma unroll
                for (int nt = 0; nt < 4; nt++) {
                    float ge = __shfl_xor_sync(0xffffffffu, v0[nt], 4);
                    float go = __shfl_xor_sync(0xffffffffu, v1[nt], 4);
                    int dloc = nt * 8 + 2 * c;
                    float p0, p1; int d;
                    if (evenr) { p0 = v0[nt]; p1 = ge;     d = dloc; }
                    else       { p0 = go;     p1 = v1[nt]; d = dloc + 1; }
                    uint32_t hh, ll;
                    bfsplit2(p0, p1, hh, ll);
                    size_t w = (bh * HD + d) * 512 + np;
                    g_vth[w] = hh; g_vtl[w] = ll;
                }
            }
        }
    }
}

// ---------------- proj GEMM (A from planes, W inline convert) ----------------
__global__ void __launch_bounds__(256) gemm_proj(const float* __restrict__ W,
                                                 const float* __restrict__ bias,
                                                 float* __restrict__ C) {
    extern __shared__ uint32_t smg[];
    uint32_t* Ah = smg;
    uint32_t* Al = Ah + 128 * 20;
    uint32_t* Wh = Al + 128 * 20;
    uint32_t* Wl = Wh + 64 * 20;
    const int bm = blockIdx.y * 128, bn = blockIdx.x * 64;
    const int tid = threadIdx.x, lane = tid & 31, warp = tid >> 5;
    const int wm = (warp >> 1) * 32, wn = (warp & 1) * 32;
    const int r = lane >> 2, c = lane & 3;
    const int K = CDIM;

    float acc[2][4][4];
#pragma unroll
    for (int mt = 0; mt < 2; mt++)
#pragma unroll
        for (int nt = 0; nt < 4; nt++)
#pragma unroll
            for (int q = 0; q < 4; q++) acc[mt][nt][q] = 0.f;

    uint2 pah[4], pal[4];
    float4 pw[2];
#pragma unroll
    for (int i = 0; i < 4; i++) {
        int v = tid + i * 256; int row = v >> 3, wq = (v & 7) * 2;
        pah[i] = *(const uint2*)&g_aoh[(size_t)(bm + row) * 128 + wq];
        pal[i] = *(const uint2*)&g_aol[(size_t)(bm + row) * 128 + wq];
    }
#pragma unroll
    for (int i = 0; i < 2; i++) {
        int v = tid + i * 256; int row = v >> 3, kq = (v & 7) * 4;
        pw[i] = *(const float4*)&W[(size_t)(bn + row) * K + kq];
    }

    for (int k0 = 0; k0 < K; k0 += 32) {
#pragma unroll
        for (int i = 0; i < 4; i++) {
            int v = tid + i * 256; int row = v >> 3, wq = (v & 7) * 2;
            *(uint2*)&Ah[row * 20 + wq] = pah[i];
            *(uint2*)&Al[row * 20 + wq] = pal[i];
        }
#pragma unroll
        for (int i = 0; i < 2; i++) {
            int v = tid + i * 256; int row = v >> 3, kq = (v & 7) * 4;
            uint32_t h, l;
            bfsplit2(pw[i].x, pw[i].y, h, l);
            Wh[row * 20 + (kq >> 1)] = h;  Wl[row * 20 + (kq >> 1)] = l;
            bfsplit2(pw[i].z, pw[i].w, h, l);
            Wh[row * 20 + (kq >> 1) + 1] = h;  Wl[row * 20 + (kq >> 1) + 1] = l;
        }
        __syncthreads();
        if (k0 + 32 < K) {
#pragma unroll
            for (int i = 0; i < 4; i++) {
                int v = tid + i * 256; int row = v >> 3, wq = (v & 7) * 2;
                pah[i] = *(const uint2*)&g_aoh[(size_t)(bm + row) * 128 + (k0 + 32) / 2 + wq];
                pal[i] = *(const uint2*)&g_aol[(size_t)(bm + row) * 128 + (k0 + 32) / 2 + wq];
            }
#pragma unroll
            for (int i = 0; i < 2; i++) {
                int v = tid + i * 256; int row = v >> 3, kq = (v & 7) * 4;
                pw[i] = *(const float4*)&W[(size_t)(bn + row) * K + k0 + 32 + kq];
            }
        }
#pragma unroll
        for (int kt = 0; kt < 2; kt++) {
            uint32_t ah[2][4], al[2][4];
#pragma unroll
            for (int mt = 0; mt < 2; mt++) {
                int r0 = (wm + mt * 16 + r) * 20 + kt * 8 + c;
                int r1 = r0 + 8 * 20;
                ah[mt][0] = Ah[r0];     al[mt][0] = Al[r0];
                ah[mt][1] = Ah[r1];     al[mt][1] = Al[r1];
                ah[mt][2] = Ah[r0 + 4]; al[mt][2] = Al[r0 + 4];
                ah[mt][3] = Ah[r1 + 4]; al[mt][3] = Al[r1 + 4];
            }
#pragma unroll
            for (int nt = 0; nt < 4; nt++) {
                int w0 = (wn + nt * 8 + r) * 20 + kt * 8 + c;
                uint32_t bh0 = Wh[w0], bh1 = Wh[w0 + 4];
                uint32_t bl0 = Wl[w0], bl1 = Wl[w0 + 4];
#pragma unroll
                for (int mt = 0; mt < 2; mt++) {
                    mma_bf16(acc[mt][nt], ah[mt][0], ah[mt][1], ah[mt][2], ah[mt][3], bh0, bh1);
                    mma_bf16(acc[mt][nt], al[mt][0], al[mt][1], al[mt][2], al[mt][3], bh0, bh1);
                    mma_bf16(acc[mt][nt], ah[mt][0], ah[mt][1], ah[mt][2], ah[mt][3], bl0, bl1);
                }
            }
        }
        __syncthreads();
    }
#pragma unroll
    for (int mt = 0; mt < 2; mt++) {
        int row0 = bm + wm + mt * 16 + r;
        int row1 = row0 + 8;
#pragma unroll
        for (int nt = 0; nt < 4; nt++) {
            int n = bn + wn + nt * 8 + 2 * c;
            float b0 = bias[n], b1 = bias[n + 1];
            *(float2*)&C[(size_t)row0 * CDIM + n] = make_float2(acc[mt][nt][0] + b0, acc[mt][nt][1] + b1);
            *(float2*)&C[(size_t)row1 * CDIM + n] = make_float2(acc[mt][nt][2] + b0, acc[mt][nt][3] + b1);
        }
    }
}

// ---------------- attention: 2x2 (query,key) warp split ----------------------
// Fixed-max base-2 softmax; 3-mma PV (Ph*Vh + Pl*Vh + Ph*Vl) for precision.
#define ABUF 4864   // words: Kh 1280 | Kl 1280 | Vh 1152 | Vl 1152

__global__ __launch_bounds__(128, 4) void attn_tc() {
    extern __shared__ uint32_t smw[];

    const int n0 = blockIdx.x * 64;
    const int h  = blockIdx.y;
    const int b  = blockIdx.z;
    const int tid = threadIdx.x, lane = tid & 31, warp = tid >> 5;
    const int qg = warp >> 1, kg = warp & 1;
    const int r = lane >> 2, c = lane & 3;
    const size_t bh = (size_t)(b * NHEADS + h);

    const uint32_t* kh_g  = g_kh  + bh * NN * 16;
    const uint32_t* kl_g  = g_kl  + bh * NN * 16;
    const uint32_t* vth_g = g_vth + bh * HD * 512;
    const uint32_t* vtl_g = g_vtl + bh * HD * 512;

    auto issue = [&](int kt, int buf) {
        uint32_t s0 = (uint32_t)__cvta_generic_to_shared(smw + buf * ABUF);
#pragma unroll
        for (int i = 0; i < 4; i++) {
            int v = tid + i * 128;
            int plane = v >> 8, rem = v & 255;
            int row = rem >> 2, cq = (rem & 3) * 4;
            const uint32_t* src = (plane ? kl_g : kh_g) + (size_t)(kt * 64 + row) * 16 + cq;
            cp16(s0 + (plane * 1280 + row * 20 + cq) * 4, src);
        }
#pragma unroll
        for (int i = 0; i < 4; i++) {
            int v = tid + i * 128;
            int plane = v >> 8, rem = v & 255;
            int d = rem >> 3, cq = (rem & 7) * 4;
            const uint32_t* src = (plane ? vtl_g : vth_g) + (size_t)d * 512 + kt * 32 + cq;
            cp16(s0 + (2560 + plane * 1152 + d * 36 + cq) * 4, src);
        }
    };

    issue(0, 0);
    asm volatile("cp.async.commit_group;");

    // Q fragments: rows n0 + qg*32 + mt*16 + {r, r+8}
    const uint32_t* qh_g = g_q2h + bh * NN * 16;
    const uint32_t* ql_g = g_q2l + bh * NN * 16;
    uint32_t qh[2][2][4], ql[2][2][4];
#pragma unroll
    for (int mt = 0; mt < 2; mt++) {
        int nr0 = n0 + qg * 32 + mt * 16 + r;
#pragma unroll
        for (int ks = 0; ks < 2; ks++) {
            qh[mt][ks][0] = qh_g[(size_t)nr0 * 16 + ks * 8 + c];
            qh[mt][ks][1] = qh_g[(size_t)(nr0 + 8) * 16 + ks * 8 + c];
            qh[mt][ks][2] = qh_g[(size_t)nr0 * 16 + ks * 8 + 4 + c];
            qh[mt][ks][3] = qh_g[(size_t)(nr0 + 8) * 16 + ks * 8 + 4 + c];
            ql[mt][ks][0] = ql_g[(size_t)nr0 * 16 + ks * 8 + c];
            ql[mt][ks][1] = ql_g[(size_t)(nr0 + 8) * 16 + ks * 8 + c];
            ql[mt][ks][2] = ql_g[(size_t)nr0 * 16 + ks * 8 + 4 + c];
            ql[mt][ks][3] = ql_g[(size_t)(nr0 + 8) * 16 + ks * 8 + 4 + c];
        }
    }
    const float tm = g_tabmax[h];
    float Cc[2][2];
#pragma unroll
    for (int mt = 0; mt < 2; mt++) {
        int nr0 = n0 + qg * 32 + mt * 16 + r;
        Cc[mt][0] = g_smax[bh * NN + nr0] + tm;
        Cc[mt][1] = g_smax[bh * NN + nr0 + 8] + tm;
    }
    const uint32_t* bp[2][2];
#pragma unroll
    for (int mt = 0; mt < 2; mt++)
#pragma unroll
        for (int half = 0; half < 2; half++)
            bp[mt][half] = g_bias + ((size_t)h * NN + n0 + qg * 32 + mt * 16 + half * 8 + r) * 512
                           + kg * 16 + c;

    float O[2][4][4] = {};
    float ll[2][2] = {};

    for (int kt = 0; kt < 16; kt++) {
        __syncthreads();
        if (kt < 15) {
            issue(kt + 1, (kt + 1) & 1);
            asm volatile("cp.async.commit_group;");
            asm volatile("cp.async.wait_group 1;");
        } else {
            asm volatile("cp.async.wait_group 0;");
        }
        __syncthreads();

        const uint32_t* Khb = smw + (kt & 1) * ABUF;
        const uint32_t* Klb = Khb + 1280;
        const uint32_t* Vhb = Khb + 2560;
        const uint32_t* Vlb = Khb + 3712;

        uint32_t bw[2][2][4];
#pragma unroll
        for (int mt = 0; mt < 2; mt++)
#pragma unroll
            for (int half = 0; half < 2; half++)
#pragma unroll
                for (int j = 0; j < 4; j++)
                    bw[mt][half][j] = bp[mt][half][kt * 32 + j * 4];

        // ---- S = Q K^T over this warp's 32 keys (3-plane bf16) ----
        float sc[2][4][4] = {};
#pragma unroll
        for (int j = 0; j < 4; j++) {
            int rowb = (kg * 32 + j * 8 + r) * 20;
#pragma unroll
            for (int ks = 0; ks < 2; ks++) {
                uint32_t bh0 = Khb[rowb + ks * 8 + c], bh1 = Khb[rowb + ks * 8 + 4 + c];
                uint32_t bl0 = Klb[rowb + ks * 8 + c], bl1 = Klb[rowb + ks * 8 + 4 + c];
#pragma unroll
                for (int mt = 0; mt < 2; mt++) {
                    mma_bf16(sc[mt][j], qh[mt][ks][0], qh[mt][ks][1], qh[mt][ks][2], qh[mt][ks][3], bh0, bh1);
                    mma_bf16(sc[mt][j], ql[mt][ks][0], ql[mt][ks][1], ql[mt][ks][2], ql[mt][ks][3], bh0, bh1);
                    mma_bf16(sc[mt][j], qh[mt][ks][0], qh[mt][ks][1], qh[mt][ks][2], qh[mt][ks][3], bl0, bl1);
                }
            }
        }

        // ---- fixed-max base-2 softmax: p = exp2(S + bias - C), hi/lo P planes ----
        uint32_t phr[2][4], phr8[2][4], plr[2][4], plr8[2][4];
#pragma unroll
        for (int mt = 0; mt < 2; mt++) {
            float s0 = 0.f, s1 = 0.f;
#pragma unroll
            for (int j = 0; j < 4; j++) {
                float p0 = ex2f(sc[mt][j][0] + __uint_as_float(bw[mt][0][j] << 16)         - Cc[mt][0]);
                float p1 = ex2f(sc[mt][j][1] + __uint_as_float(bw[mt][0][j] & 0xffff0000u) - Cc[mt][0]);
                float p2 = ex2f(sc[mt][j][2] + __uint_as_float(bw[mt][1][j] << 16)         - Cc[mt][1]);
                float p3 = ex2f(sc[mt][j][3] + __uint_as_float(bw[mt][1][j] & 0xffff0000u) - Cc[mt][1]);
                s0 += p0 + p1; s1 += p2 + p3;
                bfsplit2(p0, p1, phr[mt][j],  plr[mt][j]);
                bfsplit2(p2, p3, phr8[mt][j], plr8[mt][j]);
            }
            ll[mt][0] += s0; ll[mt][1] += s1;
        }

        // ---- O += P @ V over this warp's 32 keys (3-term) ----
#pragma unroll
        for (int kk = 0; kk < 2; kk++) {
#pragma unroll
            for (int jd = 0; jd < 4; jd++) {
                int w0 = (jd * 8 + r) * 36 + kg * 16 + kk * 8 + c;
                uint32_t vh0 = Vhb[w0], vh1 = Vhb[w0 + 4];
                uint32_t vl0 = Vlb[w0], vl1 = Vlb[w0 + 4];
#pragma unroll
                for (int mt = 0; mt < 2; mt++) {
                    mma_bf16(O[mt][jd], phr[mt][2 * kk], phr8[mt][2 * kk],
                             phr[mt][2 * kk + 1], phr8[mt][2 * kk + 1], vh0, vh1);
                    mma_bf16(O[mt][jd], plr[mt][2 * kk], plr8[mt][2 * kk],
                             plr[mt][2 * kk + 1], plr8[mt][2 * kk + 1], vh0, vh1);
                    mma_bf16(O[mt][jd], phr[mt][2 * kk], phr8[mt][2 * kk],
                             phr[mt][2 * kk + 1], phr8[mt][2 * kk + 1], vl0, vl1);
                }
            }
        }
    }

    // ---- merge the two key-halves, normalize, write bf16 hi/lo planes ----
#pragma unroll
    for (int mt = 0; mt < 2; mt++)
#pragma unroll
        for (int half = 0; half < 2; half++) {
            ll[mt][half] += __shfl_xor_sync(0xffffffffu, ll[mt][half], 1);
            ll[mt][half] += __shfl_xor_sync(0xffffffffu, ll[mt][half], 2);
        }

    float* xb = (float*)smw;                 // loop done; buffers reusable
    int slot = qg * (32 * 37) + lane * 37;
    if (kg == 1) {
#pragma unroll
        for (int mt = 0; mt < 2; mt++) {
#pragma unroll
            for (int jd = 0; jd < 4; jd++)
#pragma unroll
                for (int q = 0; q < 4; q++)
                    xb[slot + mt * 16 + jd * 4 + q] = O[mt][jd][q];
            xb[slot + 32 + mt * 2 + 0] = ll[mt][0];
            xb[slot + 32 + mt * 2 + 1] = ll[mt][1];
        }
    }
    __syncthreads();
    if (kg == 0) {
#pragma unroll
        for (int mt = 0; mt < 2; mt++) {
            float lt0 = ll[mt][0] + xb[slot + 32 + mt * 2 + 0];
            float lt1 = ll[mt][1] + xb[slot + 32 + mt * 2 + 1];
            float i0 = 1.f / lt0, i1 = 1.f / lt1;
            int nr0 = n0 + qg * 32 + mt * 16 + r;
            size_t base0 = (size_t)(b * NN + nr0) * 128 + h * 16;
            size_t base1 = (size_t)(b * NN + nr0 + 8) * 128 + h * 16;
#pragma unroll
            for (int jd = 0; jd < 4; jd++) {
                float o0 = (O[mt][jd][0] + xb[slot + mt * 16 + jd * 4 + 0]) * i0;
                float o1 = (O[mt][jd][1] + xb[slot + mt * 16 + jd * 4 + 1]) * i0;
                float o2 = (O[mt][jd][2] + xb[slot + mt * 16 + jd * 4 + 2]) * i1;
                float o3 = (O[mt][jd][3] + xb[slot + mt * 16 + jd * 4 + 3]) * i1;
                uint32_t hh, llw;
                bfsplit2(o0, o1, hh, llw);
                g_aoh[base0 + jd * 4 + c] = hh;
                g_aol[base0 + jd * 4 + c] = llw;
                bfsplit2(o2, o3, hh, llw);
                g_aoh[base1 + jd * 4 + c] = hh;
                g_aol[base1 + jd * 4 + c] = llw;
            }
        }
    }
}

// ---------------- launch ------------------------------------------------------
extern "C" void kernel_launch(void* const* d_in, const int* in_sizes, int n_in,
                              void* d_out, int out_size) {
    int s = (n_in >= 15) ? 0 : -2;
    const float* x       = (const float*)d_in[0];
    const int*   rpi     = (const int*)  d_in[3 + s];
    const float* coords  = (const float*)d_in[4 + s];
    const float* qkv_w   = (const float*)d_in[5 + s];
    const float* qkv_b   = (const float*)d_in[6 + s];
    const float* qe      = (const float*)d_in[7 + s];
    const float* temp    = (const float*)d_in[8 + s];
    const float* proj_w  = (const float*)d_in[9 + s];
    const float* proj_b  = (const float*)d_in[10 + s];
    const float* fc1w    = (const float*)d_in[11 + s];
    const float* fc1b    = (const float*)d_in[12 + s];
    const float* fc2w    = (const float*)d_in[13 + s];
    const float* fc2b    = (const float*)d_in[14 + s];
    float* out = (float*)d_out;

    uint32_t *p_xh, *p_xl;
    cudaGetSymbolAddress((void**)&p_xh, g_xh);
    cudaGetSymbolAddress((void**)&p_xl, g_xl);

    // pre-split x into bf16 hi/lo planes (removes 12x-redundant per-tile cvt)
    conv_split<<<(BB * NN * 128 / 2 + 255) / 256, 256>>>(x, p_xh, p_xl, BB * NN * 128);

    cpb_kernel<<<(TABLE_SZ + 31) / 32, 256>>>(coords, fc1w, fc1b, fc2w, fc2b);
    bias_expand<<<NHEADS * 64, 256>>>(rpi);

    size_t gemm_smem = (2 * 128 * 20 + 2 * 64 * 20) * sizeof(uint32_t);   // 30.7 KB
    cudaFuncSetAttribute(gemm_qkv_fused, cudaFuncAttributeMaxDynamicSharedMemorySize, (int)gemm_smem);
    cudaFuncSetAttribute(gemm_proj, cudaFuncAttributeMaxDynamicSharedMemorySize, (int)gemm_smem);

    gemm_qkv_fused<<<dim3(768 / 64, (BB * NN) / 128), 256, gemm_smem>>>(
        qkv_w, qkv_b, qe, temp);

    {
        size_t smem = 2 * ABUF * sizeof(uint32_t);    // 38.9 KB
        cudaFuncSetAttribute(attn_tc, cudaFuncAttributeMaxDynamicSharedMemorySize, (int)smem);
        attn_tc<<<dim3(16, NHEADS, BB), 128, smem>>>();
    }

    gemm_proj<<<dim3(CDIM / 64, (BB * NN) / 128), 256, gemm_smem>>>(proj_w, proj_b, out);
}

// round 12
// speedup vs baseline: 1.1406x; 1.1406x over previous
#include <cuda_runtime.h>
#include <math.h>
#include <stdint.h>

#define BB      8
#define NHEADS  8
#define HD      32
#define NN      1024
#define CDIM    256
#define TABLE_SZ 3969
#define CPBH    512
#define LOG2E   1.4426950408889634f

// ---------------- scratch -----------------------------------------------------
// Q/K: bf16 hi/lo planes, [(b*8+h)*1024 + n]*16 + dpair (low16 = even d)
// V  : fp16 hi/lo planes, [(b*8+h)*32 + d]*512 + n/2 (low16 = even n), transposed
__device__ __align__(16) uint32_t g_q2h[BB * NHEADS * NN * 16];
__device__ __align__(16) uint32_t g_q2l[BB * NHEADS * NN * 16];
__device__ __align__(16) uint32_t g_kh [BB * NHEADS * NN * 16];
__device__ __align__(16) uint32_t g_kl [BB * NHEADS * NN * 16];
__device__ __align__(16) uint32_t g_vth[BB * NHEADS * HD * (NN / 2)];
__device__ __align__(16) uint32_t g_vtl[BB * NHEADS * HD * (NN / 2)];
__device__ __align__(16) uint32_t g_bias[NHEADS * NN * (NN / 2)];    // bf16x2 (base-2)
__device__ float g_tab[NHEADS * TABLE_SZ];     // scaled by log2e
__device__ float g_tabmax[NHEADS];
__device__ float g_smax[BB * NHEADS * NN];     // ||qs_n|| (base-2 units)
__device__ float g_ao [BB * NN * CDIM];

// ---------------- helpers -----------------------------------------------------
__device__ __forceinline__ uint32_t bf16x2(float lo, float hi) {
    uint32_t d;
    asm("cvt.rn.bf16x2.f32 %0, %1, %2;" : "=r"(d) : "f"(hi), "f"(lo));
    return d;
}
__device__ __forceinline__ void bfsplit2(float x0, float x1, uint32_t &hi, uint32_t &lo) {
    uint32_t h = bf16x2(x0, x1);
    float r0 = x0 - __uint_as_float(h << 16);
    float r1 = x1 - __uint_as_float(h & 0xffff0000u);
    hi = h;
    lo = bf16x2(r0, r1);
}
__device__ __forceinline__ uint32_t f16x2(float lo, float hi) {
    uint32_t d;
    asm("cvt.rn.f16x2.f32 %0, %1, %2;" : "=r"(d) : "f"(hi), "f"(lo));
    return d;
}
__device__ __forceinline__ void f16split2(float x0, float x1, uint32_t &hi, uint32_t &lo) {
    uint32_t h = f16x2(x0, x1);
    float h0, h1;
    asm("{\n\t.reg .f16 a, b;\n\tmov.b32 {a, b}, %2;\n\t"
        "cvt.f32.f16 %0, a;\n\tcvt.f32.f16 %1, b;\n\t}"
        : "=f"(h0), "=f"(h1) : "r"(h));
    hi = h;
    lo = f16x2(x0 - h0, x1 - h1);
}
__device__ __forceinline__ float ex2f(float x) {
    float y;
    asm("ex2.approx.f32 %0, %1;" : "=f"(y) : "f"(x));
    return y;
}
__device__ __forceinline__ void mma_bf16(float c[4],
                                         uint32_t a0, uint32_t a1, uint32_t a2, uint32_t a3,
                                         uint32_t b0, uint32_t b1) {
    asm volatile(
        "mma.sync.aligned.m16n8k16.row.col.f32.bf16.bf16.f32 "
        "{%0,%1,%2,%3}, {%4,%5,%6,%7}, {%8,%9}, {%0,%1,%2,%3};"
        : "+f"(c[0]), "+f"(c[1]), "+f"(c[2]), "+f"(c[3])
        : "r"(a0), "r"(a1), "r"(a2), "r"(a3), "r"(b0), "r"(b1));
}
__device__ __forceinline__ void mma_f16(float c[4],
                                        uint32_t a0, uint32_t a1, uint32_t a2, uint32_t a3,
                                        uint32_t b0, uint32_t b1) {
    asm volatile(
        "mma.sync.aligned.m16n8k16.row.col.f32.f16.f16.f32 "
        "{%0,%1,%2,%3}, {%4,%5,%6,%7}, {%8,%9}, {%0,%1,%2,%3};"
        : "+f"(c[0]), "+f"(c[1]), "+f"(c[2]), "+f"(c[3])
        : "r"(a0), "r"(a1), "r"(a2), "r"(a3), "r"(b0), "r"(b1));
}
__device__ __forceinline__ void cp16(uint32_t dst, const void* src) {
    asm volatile("cp.async.cg.shared.global [%0], [%1], 16;" :: "r"(dst), "l"(src));
}

// ---------------- CPB MLP ------------------------------------------------------
__global__ __launch_bounds__(256) void cpb_kernel(const float* __restrict__ coords,
                                                  const float* __restrict__ fc1w,
                                                  const float* __restrict__ fc1b,
                                                  const float* __restrict__ fc2w,
                                                  const float* __restrict__ fc2b) {
    __shared__ float s_w1[CPBH * 2];
    __shared__ float s_b1[CPBH];
    __shared__ float s_w2[NHEADS * CPBH];
    const int tid = threadIdx.x;
    for (int i = tid; i < CPBH * 2; i += 256) s_w1[i] = fc1w[i];
    for (int i = tid; i < CPBH; i += 256) s_b1[i] = fc1b[i];
    for (int i = tid; i < NHEADS * CPBH; i += 256) s_w2[i] = fc2w[i];
    __syncthreads();
    const int warp = tid >> 5, lane = tid & 31;
#pragma unroll
    for (int e = 0; e < 4; e++) {
        int t = blockIdx.x * 32 + warp * 4 + e;
        if (t >= TABLE_SZ) continue;
        float c0 = coords[2 * t], c1 = coords[2 * t + 1];
        float acc[NHEADS];
#pragma unroll
        for (int h = 0; h < NHEADS; h++) acc[h] = 0.f;
#pragma unroll 4
        for (int j = lane; j < CPBH; j += 32) {
            float hv = fmaxf(c0 * s_w1[2 * j] + c1 * s_w1[2 * j + 1] + s_b1[j], 0.f);
#pragma unroll
            for (int h = 0; h < NHEADS; h++) acc[h] += hv * s_w2[h * CPBH + j];
        }
#pragma unroll
        for (int h = 0; h < NHEADS; h++) {
#pragma unroll
            for (int o = 16; o; o >>= 1) acc[h] += __shfl_xor_sync(0xffffffffu, acc[h], o);
            if (lane == 0) g_tab[h * TABLE_SZ + t] = (acc[h] + fc2b[h]) * LOG2E;
        }
    }
}

// ---------------- bias expand + per-head max ------------------------------------
__global__ __launch_bounds__(256) void bias_expand(const int* __restrict__ rpi) {
    __shared__ float tab_s[TABLE_SZ];
    __shared__ float redm[8];
    int h = blockIdx.x >> 6;
    int chunk = blockIdx.x & 63;
    for (int i = threadIdx.x; i < TABLE_SZ; i += 256) tab_s[i] = g_tab[h * TABLE_SZ + i];
    __syncthreads();
    if (chunk == 0) {
        float m = -1e30f;
        for (int i = threadIdx.x; i < TABLE_SZ; i += 256) m = fmaxf(m, tab_s[i]);
#pragma unroll
        for (int o = 16; o; o >>= 1) m = fmaxf(m, __shfl_xor_sync(0xffffffffu, m, o));
        if ((threadIdx.x & 31) == 0) redm[threadIdx.x >> 5] = m;
        __syncthreads();
        if (threadIdx.x == 0) {
            float mm = redm[0];
            for (int w = 1; w < 8; w++) mm = fmaxf(mm, redm[w]);
            g_tabmax[h] = mm;
        }
    }
    for (int i = threadIdx.x; i < 16 * 512; i += 256) {
        int nl = i >> 9, mw = i & 511;
        int n = chunk * 16 + nl;
        int2 id = *(const int2*)&rpi[(size_t)n * NN + 2 * mw];
        g_bias[((size_t)h * NN + n) * 512 + mw] = bf16x2(tab_s[id.x], tab_s[id.y]);
    }
}

// ---------------- fused qkv GEMM + l2norm + split (dbuf, 1 sync/tile) ----------
#define GBUF 7680   // words per buffer: Ah 2560 | Al 2560 | Wh 1280 | Wl 1280

__global__ __launch_bounds__(256) void gemm_qkv_fused(
        const float* __restrict__ A, const float* __restrict__ W,
        const float* __restrict__ bias,
        const float* __restrict__ qe, const float* __restrict__ temp) {
    extern __shared__ uint32_t smg[];
    const int bm = blockIdx.y * 128, bn = blockIdx.x * 64;
    const int tid = threadIdx.x, lane = tid & 31, warp = tid >> 5;
    const int wm = (warp >> 1) * 32, wn = (warp & 1) * 32;
    const int r = lane >> 2, c = lane & 3;
    const int K = CDIM;

    float acc[2][4][4];
#pragma unroll
    for (int mt = 0; mt < 2; mt++)
#pragma unroll
        for (int nt = 0; nt < 4; nt++)
#pragma unroll
            for (int q = 0; q < 4; q++) acc[mt][nt][q] = 0.f;

    float4 pa[4], pw[2];
    auto load_tile = [&](int k0) {
#pragma unroll
        for (int i = 0; i < 4; i++) {
            int v = tid + i * 256; int row = v >> 3, kq = (v & 7) * 4;
            pa[i] = *(const float4*)&A[(size_t)(bm + row) * K + k0 + kq];
        }
#pragma unroll
        for (int i = 0; i < 2; i++) {
            int v = tid + i * 256; int row = v >> 3, kq = (v & 7) * 4;
            pw[i] = *(const float4*)&W[(size_t)(bn + row) * K + k0 + kq];
        }
    };
    auto store_tile = [&](int buf) {
        uint32_t* Ah = smg + buf * GBUF;
        uint32_t* Al = Ah + 2560;
        uint32_t* Wh = Ah + 5120;
        uint32_t* Wl = Ah + 6400;
#pragma unroll
        for (int i = 0; i < 4; i++) {
            int v = tid + i * 256; int row = v >> 3, kq = (v & 7) * 4;
            uint32_t h, l;
            bfsplit2(pa[i].x, pa[i].y, h, l);
            Ah[row * 20 + (kq >> 1)] = h;  Al[row * 20 + (kq >> 1)] = l;
            bfsplit2(pa[i].z, pa[i].w, h, l);
            Ah[row * 20 + (kq >> 1) + 1] = h;  Al[row * 20 + (kq >> 1) + 1] = l;
        }
#pragma unroll
        for (int i = 0; i < 2; i++) {
            int v = tid + i * 256; int row = v >> 3, kq = (v & 7) * 4;
            uint32_t h, l;
            bfsplit2(pw[i].x, pw[i].y, h, l);
            Wh[row * 20 + (kq >> 1)] = h;  Wl[row * 20 + (kq >> 1)] = l;
            bfsplit2(pw[i].z, pw[i].w, h, l);
            Wh[row * 20 + (kq >> 1) + 1] = h;  Wl[row * 20 + (kq >> 1) + 1] = l;
        }
    };

    load_tile(0);
    store_tile(0);
    load_tile(32);

    const int NT = K / 32;
    for (int t = 0; t < NT; t++) {
        __syncthreads();
        if (t + 1 < NT) {
            store_tile((t + 1) & 1);
            if (t + 2 < NT) load_tile((t + 2) * 32);
        }
        const uint32_t* Ahb = smg + (t & 1) * GBUF;
        const uint32_t* Alb = Ahb + 2560;
        const uint32_t* Whb = Ahb + 5120;
        const uint32_t* Wlb = Ahb + 6400;
#pragma unroll
        for (int kt = 0; kt < 2; kt++) {
            uint32_t ah[2][4], al[2][4];
#pragma unroll
            for (int mt = 0; mt < 2; mt++) {
                int r0 = (wm + mt * 16 + r) * 20 + kt * 8 + c;
                int r1 = r0 + 8 * 20;
                ah[mt][0] = Ahb[r0];     al[mt][0] = Alb[r0];
                ah[mt][1] = Ahb[r1];     al[mt][1] = Alb[r1];
                ah[mt][2] = Ahb[r0 + 4]; al[mt][2] = Alb[r0 + 4];
                ah[mt][3] = Ahb[r1 + 4]; al[mt][3] = Alb[r1 + 4];
            }
#pragma unroll
            for (int nt = 0; nt < 4; nt++) {
                int w0 = (wn + nt * 8 + r) * 20 + kt * 8 + c;
                uint32_t bh0 = Whb[w0], bh1 = Whb[w0 + 4];
                uint32_t bl0 = Wlb[w0], bl1 = Wlb[w0 + 4];
#pragma unroll
                for (int mt = 0; mt < 2; mt++) {
                    mma_bf16(acc[mt][nt], ah[mt][0], ah[mt][1], ah[mt][2], ah[mt][3], bh0, bh1);
                    mma_bf16(acc[mt][nt], al[mt][0], al[mt][1], al[mt][2], al[mt][3], bh0, bh1);
                    mma_bf16(acc[mt][nt], ah[mt][0], ah[mt][1], ah[mt][2], ah[mt][3], bl0, bl1);
                }
            }
        }
    }

    // ---- fused epilogue ----
    const int col_base = bn + wn;
    const int region = col_base >> 8;             // 0=q, 1=k, 2=v
    const int head = (col_base >> 5) & 7;
    float scale_h = 0.f, qe0[4], qe1[4];
    if (region == 0) {
        scale_h = log1pf(expf(temp[head])) * logf(1024.0f) * LOG2E;
#pragma unroll
        for (int nt = 0; nt < 4; nt++) {
            qe0[nt] = qe[head * HD + nt * 8 + 2 * c];
            qe1[nt] = qe[head * HD + nt * 8 + 2 * c + 1];
        }
    }
#pragma unroll
    for (int mt = 0; mt < 2; mt++) {
#pragma unroll
        for (int half = 0; half < 2; half++) {
            int row = bm + wm + mt * 16 + r + half * 8;
            int bq = row >> 10, n = row & 1023;
            float v0[4], v1[4];
#pragma unroll
            for (int nt = 0; nt < 4; nt++) {
                int cg = col_base + nt * 8 + 2 * c;
                v0[nt] = acc[mt][nt][half * 2]     + bias[cg];
                v1[nt] = acc[mt][nt][half * 2 + 1] + bias[cg + 1];
            }
            if (region < 2) {
                float ss = 0.f;
#pragma unroll
                for (int nt = 0; nt < 4; nt++) ss += v0[nt] * v0[nt] + v1[nt] * v1[nt];
                ss += __shfl_xor_sync(0xffffffffu, ss, 1);
                ss += __shfl_xor_sync(0xffffffffu, ss, 2);
                float inv = 1.f / fmaxf(sqrtf(ss), 1e-12f);
                size_t base = ((size_t)(bq * 8 + head) * NN + n) * 16;
                float ss2 = 0.f;
#pragma unroll
                for (int nt = 0; nt < 4; nt++) {
                    float a = v0[nt] * inv, bv = v1[nt] * inv;
                    if (region == 0) {
                        a  = (a  + qe0[nt]) * scale_h;
                        bv = (bv + qe1[nt]) * scale_h;
                        ss2 += a * a + bv * bv;
                    }
                    uint32_t hh, ll;
                    bfsplit2(a, bv, hh, ll);
                    size_t w = base + nt * 4 + c;
                    if (region == 0) { g_q2h[w] = hh; g_q2l[w] = ll; }
                    else             { g_kh[w]  = hh; g_kl[w]  = ll; }
                }
                if (region == 0) {
                    ss2 += __shfl_xor_sync(0xffffffffu, ss2, 1);
                    ss2 += __shfl_xor_sync(0xffffffffu, ss2, 2);
                    if (c == 0)
                        g_smax[(size_t)(bq * 8 + head) * NN + n] = sqrtf(ss2);
                }
            } else {
                size_t bh = (size_t)(bq * 8 + head);
                int np = n >> 1;
                bool evenr = ((r & 1) == 0);
#pragma unroll
                for (int nt = 0; nt < 4; nt++) {
                    float ge = __shfl_xor_sync(0xffffffffu, v0[nt], 4);
                    float go = __shfl_xor_sync(0xffffffffu, v1[nt], 4);
                    int dloc = nt * 8 + 2 * c;
                    float p0, p1; int d;
                    if (evenr) { p0 = v0[nt]; p1 = ge;     d = dloc; }
                    else       { p0 = go;     p1 = v1[nt]; d = dloc + 1; }
                    uint32_t hh, ll;
                    f16split2(p0, p1, hh, ll);      // V planes are fp16 now
                    size_t w = (bh * HD + d) * 512 + np;
                    g_vth[w] = hh; g_vtl[w] = ll;
                }
            }
        }
    }
}

// ---------------- proj GEMM (dbuf, 1 sync/tile) ---------------------------------
__global__ void __launch_bounds__(256) gemm_tc(const float* __restrict__ A,
                                               const float* __restrict__ W,
                                               const float* __restrict__ bias,
                                               float* __restrict__ C,
                                               int M, int N, int K) {
    extern __shared__ uint32_t smg[];
    const int bm = blockIdx.y * 128, bn = blockIdx.x * 64;
    const int tid = threadIdx.x, lane = tid & 31, warp = tid >> 5;
    const int wm = (warp >> 1) * 32, wn = (warp & 1) * 32;
    const int r = lane >> 2, c = lane & 3;

    float acc[2][4][4];
#pragma unroll
    for (int mt = 0; mt < 2; mt++)
#pragma unroll
        for (int nt = 0; nt < 4; nt++)
#pragma unroll
            for (int q = 0; q < 4; q++) acc[mt][nt][q] = 0.f;

    float4 pa[4], pw[2];
    auto load_tile = [&](int k0) {
#pragma unroll
        for (int i = 0; i < 4; i++) {
            int v = tid + i * 256; int row = v >> 3, kq = (v & 7) * 4;
            pa[i] = *(const float4*)&A[(size_t)(bm + row) * K + k0 + kq];
        }
#pragma unroll
        for (int i = 0; i < 2; i++) {
            int v = tid + i * 256; int row = v >> 3, kq = (v & 7) * 4;
            pw[i] = *(const float4*)&W[(size_t)(bn + row) * K + k0 + kq];
        }
    };
    auto store_tile = [&](int buf) {
        uint32_t* Ah = smg + buf * GBUF;
        uint32_t* Al = Ah + 2560;
        uint32_t* Wh = Ah + 5120;
        uint32_t* Wl = Ah + 6400;
#pragma unroll
        for (int i = 0; i < 4; i++) {
            int v = tid + i * 256; int row = v >> 3, kq = (v & 7) * 4;
            uint32_t h, l;
            bfsplit2(pa[i].x, pa[i].y, h, l);
            Ah[row * 20 + (kq >> 1)] = h;  Al[row * 20 + (kq >> 1)] = l;
            bfsplit2(pa[i].z, pa[i].w, h, l);
            Ah[row * 20 + (kq >> 1) + 1] = h;  Al[row * 20 + (kq >> 1) + 1] = l;
        }
#pragma unroll
        for (int i = 0; i < 2; i++) {
            int v = tid + i * 256; int row = v >> 3, kq = (v & 7) * 4;
            uint32_t h, l;
            bfsplit2(pw[i].x, pw[i].y, h, l);
            Wh[row * 20 + (kq >> 1)] = h;  Wl[row * 20 + (kq >> 1)] = l;
            bfsplit2(pw[i].z, pw[i].w, h, l);
            Wh[row * 20 + (kq >> 1) + 1] = h;  Wl[row * 20 + (kq >> 1) + 1] = l;
        }
    };

    load_tile(0);
    store_tile(0);
    load_tile(32);

    const int NT = K / 32;
    for (int t = 0; t < NT; t++) {
        __syncthreads();
        if (t + 1 < NT) {
            store_tile((t + 1) & 1);
            if (t + 2 < NT) load_tile((t + 2) * 32);
        }
        const uint32_t* Ahb = smg + (t & 1) * GBUF;
        const uint32_t* Alb = Ahb + 2560;
        const uint32_t* Whb = Ahb + 5120;
        const uint32_t* Wlb = Ahb + 6400;
#pragma unroll
        for (int kt = 0; kt < 2; kt++) {
            uint32_t ah[2][4], al[2][4];
#pragma unroll
            for (int mt = 0; mt < 2; mt++) {
                int r0 = (wm + mt * 16 + r) * 20 + kt * 8 + c;
                int r1 = r0 + 8 * 20;
                ah[mt][0] = Ahb[r0];     al[mt][0] = Alb[r0];
                ah[mt][1] = Ahb[r1];     al[mt][1] = Alb[r1];
                ah[mt][2] = Ahb[r0 + 4]; al[mt][2] = Alb[r0 + 4];
                ah[mt][3] = Ahb[r1 + 4]; al[mt][3] = Alb[r1 + 4];
            }
#pragma unroll
            for (int nt = 0; nt < 4; nt++) {
                int w0 = (wn + nt * 8 + r) * 20 + kt * 8 + c;
                uint32_t bh0 = Whb[w0], bh1 = Whb[w0 + 4];
                uint32_t bl0 = Wlb[w0], bl1 = Wlb[w0 + 4];
#pragma unroll
                for (int mt = 0; mt < 2; mt++) {
                    mma_bf16(acc[mt][nt], ah[mt][0], ah[mt][1], ah[mt][2], ah[mt][3], bh0, bh1);
                    mma_bf16(acc[mt][nt], al[mt][0], al[mt][1], al[mt][2], al[mt][3], bh0, bh1);
                    mma_bf16(acc[mt][nt], ah[mt][0], ah[mt][1], ah[mt][2], ah[mt][3], bl0, bl1);
                }
            }
        }
    }
#pragma unroll
    for (int mt = 0; mt < 2; mt++) {
        int row0 = bm + wm + mt * 16 + r;
        int row1 = row0 + 8;
#pragma unroll
        for (int nt = 0; nt < 4; nt++) {
            int n = bn + wn + nt * 8 + 2 * c;
            float b0 = bias[n], b1 = bias[n + 1];
            *(float2*)&C[(size_t)row0 * N + n] = make_float2(acc[mt][nt][0] + b0, acc[mt][nt][1] + b1);
            *(float2*)&C[(size_t)row1 * N + n] = make_float2(acc[mt][nt][2] + b0, acc[mt][nt][3] + b1);
        }
    }
}

// ---------------- attention: 2x2 warp split, fp16 P/V, 1 sync/tile --------------
#define ABUF 4864   // words: Kh 1280 | Kl 1280 | Vh 1152 | Vl 1152

__global__ __launch_bounds__(128, 4) void attn_tc(float* __restrict__ out) {
    extern __shared__ uint32_t smw[];

    const int n0 = blockIdx.x * 64;
    const int h  = blockIdx.y;
    const int b  = blockIdx.z;
    const int tid = threadIdx.x, lane = tid & 31, warp = tid >> 5;
    const int qg = warp >> 1, kg = warp & 1;
    const int r = lane >> 2, c = lane & 3;
    const size_t bh = (size_t)(b * NHEADS + h);

    const uint32_t* kh_g  = g_kh  + bh * NN * 16;
    const uint32_t* kl_g  = g_kl  + bh * NN * 16;
    const uint32_t* vth_g = g_vth + bh * HD * 512;
    const uint32_t* vtl_g = g_vtl + bh * HD * 512;

    auto issue = [&](int kt, int buf) {
        uint32_t s0 = (uint32_t)__cvta_generic_to_shared(smw + buf * ABUF);
#pragma unroll
        for (int i = 0; i < 4; i++) {
            int v = tid + i * 128;
            int plane = v >> 8, rem = v & 255;
            int row = rem >> 2, cq = (rem & 3) * 4;
            const uint32_t* src = (plane ? kl_g : kh_g) + (size_t)(kt * 64 + row) * 16 + cq;
            cp16(s0 + (plane * 1280 + row * 20 + cq) * 4, src);
        }
#pragma unroll
        for (int i = 0; i < 4; i++) {
            int v = tid + i * 128;
            int plane = v >> 8, rem = v & 255;
            int d = rem >> 3, cq = (rem & 7) * 4;
            const uint32_t* src = (plane ? vtl_g : vth_g) + (size_t)d * 512 + kt * 32 + cq;
            cp16(s0 + (2560 + plane * 1152 + d * 36 + cq) * 4, src);
        }
    };

    issue(0, 0);
    asm volatile("cp.async.commit_group;");

    // Q fragments: rows n0 + qg*32 + mt*16 + {r, r+8}
    const uint32_t* qh_g = g_q2h + bh * NN * 16;
    const uint32_t* ql_g = g_q2l + bh * NN * 16;
    uint32_t qh[2][2][4], ql[2][2][4];
#pragma unroll
    for (int mt = 0; mt < 2; mt++) {
        int nr0 = n0 + qg * 32 + mt * 16 + r;
#pragma unroll
        for (int ks = 0; ks < 2; ks++) {
            qh[mt][ks][0] = qh_g[(size_t)nr0 * 16 + ks * 8 + c];
            qh[mt][ks][1] = qh_g[(size_t)(nr0 + 8) * 16 + ks * 8 + c];
            qh[mt][ks][2] = qh_g[(size_t)nr0 * 16 + ks * 8 + 4 + c];
            qh[mt][ks][3] = qh_g[(size_t)(nr0 + 8) * 16 + ks * 8 + 4 + c];
            ql[mt][ks][0] = ql_g[(size_t)nr0 * 16 + ks * 8 + c];
            ql[mt][ks][1] = ql_g[(size_t)(nr0 + 8) * 16 + ks * 8 + c];
            ql[mt][ks][2] = ql_g[(size_t)nr0 * 16 + ks * 8 + 4 + c];
            ql[mt][ks][3] = ql_g[(size_t)(nr0 + 8) * 16 + ks * 8 + 4 + c];
        }
    }
    const float tm = g_tabmax[h];
    float Cc[2][2];
#pragma unroll
    for (int mt = 0; mt < 2; mt++) {
        int nr0 = n0 + qg * 32 + mt * 16 + r;
        // shift by -15: max p = 2^15 < fp16 max (65504); never overflows
        Cc[mt][0] = g_smax[bh * NN + nr0]     + tm - 15.0f;
        Cc[mt][1] = g_smax[bh * NN + nr0 + 8] + tm - 15.0f;
    }
    const uint32_t* bp[2][2];
#pragma unroll
    for (int mt = 0; mt < 2; mt++)
#pragma unroll
        for (int half = 0; half < 2; half++)
            bp[mt][half] = g_bias + ((size_t)h * NN + n0 + qg * 32 + mt * 16 + half * 8 + r) * 512
                           + kg * 16 + c;

    float O[2][4][4] = {};
    float ll[2][2] = {};

    for (int kt = 0; kt < 16; kt++) {
        asm volatile("cp.async.wait_group 0;");
        __syncthreads();
        if (kt < 15) {
            issue(kt + 1, (kt + 1) & 1);
            asm volatile("cp.async.commit_group;");
        }

        const uint32_t* Khb = smw + (kt & 1) * ABUF;
        const uint32_t* Klb = Khb + 1280;
        const uint32_t* Vhb = Khb + 2560;
        const uint32_t* Vlb = Khb + 3712;

        uint32_t bw[2][2][4];
#pragma unroll
        for (int mt = 0; mt < 2; mt++)
#pragma unroll
            for (int half = 0; half < 2; half++)
#pragma unroll
                for (int j = 0; j < 4; j++)
                    bw[mt][half][j] = bp[mt][half][kt * 32 + j * 4];

        // ---- S = Q K^T over this warp's 32 keys (3-plane bf16) ----
        float sc[2][4][4] = {};
#pragma unroll
        for (int j = 0; j < 4; j++) {
            int rowb = (kg * 32 + j * 8 + r) * 20;
#pragma unroll
            for (int ks = 0; ks < 2; ks++) {
                uint32_t bh0 = Khb[rowb + ks * 8 + c], bh1 = Khb[rowb + ks * 8 + 4 + c];
                uint32_t bl0 = Klb[rowb + ks * 8 + c], bl1 = Klb[rowb + ks * 8 + 4 + c];
#pragma unroll
                for (int mt = 0; mt < 2; mt++) {
                    mma_bf16(sc[mt][j], qh[mt][ks][0], qh[mt][ks][1], qh[mt][ks][2], qh[mt][ks][3], bh0, bh1);
                    mma_bf16(sc[mt][j], ql[mt][ks][0], ql[mt][ks][1], ql[mt][ks][2], ql[mt][ks][3], bh0, bh1);
                    mma_bf16(sc[mt][j], qh[mt][ks][0], qh[mt][ks][1], qh[mt][ks][2], qh[mt][ks][3], bl0, bl1);
                }
            }
        }

        // ---- fixed-max base-2 softmax: p = exp2(S + bias - C) in [0, 2^15] ----
        uint32_t phr[2][4], phr8[2][4];
#pragma unroll
        for (int mt = 0; mt < 2; mt++) {
            float s0 = 0.f, s1 = 0.f;
#pragma unroll
            for (int j = 0; j < 4; j++) {
                float p0 = ex2f(sc[mt][j][0] + __uint_as_float(bw[mt][0][j] << 16)         - Cc[mt][0]);
                float p1 = ex2f(sc[mt][j][1] + __uint_as_float(bw[mt][0][j] & 0xffff0000u) - Cc[mt][0]);
                float p2 = ex2f(sc[mt][j][2] + __uint_as_float(bw[mt][1][j] << 16)         - Cc[mt][1]);
                float p3 = ex2f(sc[mt][j][3] + __uint_as_float(bw[mt][1][j] & 0xffff0000u) - Cc[mt][1]);
                s0 += p0 + p1; s1 += p2 + p3;
                phr[mt][j]  = f16x2(p0, p1);    // fp16 P: 10-bit mantissa
                phr8[mt][j] = f16x2(p2, p3);
            }
            ll[mt][0] += s0; ll[mt][1] += s1;
        }

        // ---- O += P @ V over this warp's 32 keys (fp16: Ph*Vh + Ph*Vl) ----
#pragma unroll
        for (int kk = 0; kk < 2; kk++) {
#pragma unroll
            for (int jd = 0; jd < 4; jd++) {
                int w0 = (jd * 8 + r) * 36 + kg * 16 + kk * 8 + c;
                uint32_t vh0 = Vhb[w0], vh1 = Vhb[w0 + 4];
                uint32_t vl0 = Vlb[w0], vl1 = Vlb[w0 + 4];
#pragma unroll
                for (int mt = 0; mt < 2; mt++) {
                    mma_f16(O[mt][jd], phr[mt][2 * kk], phr8[mt][2 * kk],
                            phr[mt][2 * kk + 1], phr8[mt][2 * kk + 1], vh0, vh1);
                    mma_f16(O[mt][jd], phr[mt][2 * kk], phr8[mt][2 * kk],
                            phr[mt][2 * kk + 1], phr8[mt][2 * kk + 1], vl0, vl1);
                }
            }
        }
    }

    // ---- merge the two key-halves, normalize, write ----
#pragma unroll
    for (int mt = 0; mt < 2; mt++)
#pragma unroll
        for (int half = 0; half < 2; half++) {
            ll[mt][half] += __shfl_xor_sync(0xffffffffu, ll[mt][half], 1);
            ll[mt][half] += __shfl_xor_sync(0xffffffffu, ll[mt][half], 2);
        }

    float* xb = (float*)smw;                 // loop done; buffers reusable
    int slot = qg * (32 * 37) + lane * 37;
    if (kg == 1) {
#pragma unroll
        for (int mt = 0; mt < 2; mt++) {
#pragma unroll
            for (int jd = 0; jd < 4; jd++)
#pragma unroll
                for (int q = 0; q < 4; q++)
                    xb[slot + mt * 16 + jd * 4 + q] = O[mt][jd][q];
            xb[slot + 32 + mt * 2 + 0] = ll[mt][0];
            xb[slot + 32 + mt * 2 + 1] = ll[mt][1];
        }
    }
    __syncthreads();
    if (kg == 0) {
#pragma unroll
        for (int mt = 0; mt < 2; mt++) {
            float lt0 = ll[mt][0] + xb[slot + 32 + mt * 2 + 0];
            float lt1 = ll[mt][1] + xb[slot + 32 + mt * 2 + 1];
            float i0 = 1.f / lt0, i1 = 1.f / lt1;
            int nr0 = n0 + qg * 32 + mt * 16 + r;
#pragma unroll
            for (int jd = 0; jd < 4; jd++) {
                float o0 = O[mt][jd][0] + xb[slot + mt * 16 + jd * 4 + 0];
                float o1 = O[mt][jd][1] + xb[slot + mt * 16 + jd * 4 + 1];
                float o2 = O[mt][jd][2] + xb[slot + mt * 16 + jd * 4 + 2];
                float o3 = O[mt][jd][3] + xb[slot + mt * 16 + jd * 4 + 3];
                int col = h * HD + jd * 8 + 2 * c;
                *(float2*)&out[(size_t)(b * NN + nr0) * CDIM + col] =
                    make_float2(o0 * i0, o1 * i0);
                *(float2*)&out[(size_t)(b * NN + nr0 + 8) * CDIM + col] =
                    make_float2(o2 * i1, o3 * i1);
            }
        }
    }
}

// ---------------- launch ----------------------------------------------------------
extern "C" void kernel_launch(void* const* d_in, const int* in_sizes, int n_in,
                              void* d_out, int out_size) {
    int s = (n_in >= 15) ? 0 : -2;
    const float* x       = (const float*)d_in[0];
    const int*   rpi     = (const int*)  d_in[3 + s];
    const float* coords  = (const float*)d_in[4 + s];
    const float* qkv_w   = (const float*)d_in[5 + s];
    const float* qkv_b   = (const float*)d_in[6 + s];
    const float* qe      = (const float*)d_in[7 + s];
    const float* temp    = (const float*)d_in[8 + s];
    const float* proj_w  = (const float*)d_in[9 + s];
    const float* proj_b  = (const float*)d_in[10 + s];
    const float* fc1w    = (const float*)d_in[11 + s];
    const float* fc1b    = (const float*)d_in[12 + s];
    const float* fc2w    = (const float*)d_in[13 + s];
    const float* fc2b    = (const float*)d_in[14 + s];
    float* out = (float*)d_out;

    float* p_ao;
    cudaGetSymbolAddress((void**)&p_ao, g_ao);

    cpb_kernel<<<(TABLE_SZ + 31) / 32, 256>>>(coords, fc1w, fc1b, fc2w, fc2b);
    bias_expand<<<NHEADS * 64, 256>>>(rpi);

    size_t gemm_smem = 2 * GBUF * sizeof(uint32_t);   // 61.4 KB (double buffered)
    cudaFuncSetAttribute(gemm_qkv_fused, cudaFuncAttributeMaxDynamicSharedMemorySize, (int)gemm_smem);
    cudaFuncSetAttribute(gemm_tc, cudaFuncAttributeMaxDynamicSharedMemorySize, (int)gemm_smem);

    gemm_qkv_fused<<<dim3(768 / 64, (BB * NN) / 128), 256, gemm_smem>>>(
        x, qkv_w, qkv_b, qe, temp);

    {
        size_t smem = 2 * ABUF * sizeof(uint32_t);    // 38.9 KB
        cudaFuncSetAttribute(attn_tc, cudaFuncAttributeMaxDynamicSharedMemorySize, (int)smem);
        attn_tc<<<dim3(16, NHEADS, BB), 128, smem>>>(p_ao);
    }

    gemm_tc<<<dim3(CDIM / 64, (BB * NN) / 128), 256, gemm_smem>>>(
        p_ao, proj_w, proj_b, out, BB * NN, CDIM, CDIM);
}